// round 1
// baseline (speedup 1.0000x reference)
#include <cuda_runtime.h>

#define B 128
#define DF 2048
#define KSPLIT 32
#define KCHUNK 64   // DF / KSPLIT

// Scratch (static device globals; no allocation).
__device__ float g_Gp[KSPLIT * B * B];   // split-K partial Gram
__device__ float g_G[B * B];             // reduced Gram
__device__ float g_partials[16];         // per-group loss sums

// ---------------------------------------------------------------------------
// Kernel A: split-K partial Gram. grid (2,2,32), block 256.
// Block (bx,by,bz): 64x64 output tile over K-chunk [bz*64, bz*64+64).
// SMEM stored k-major so the 4x4 register tile reads contiguous float4s.
// ---------------------------------------------------------------------------
__global__ __launch_bounds__(256) void gram_partial(const float* __restrict__ X) {
    const int tileC = blockIdx.x * 64;
    const int tileR = blockIdx.y * 64;
    const int kBase = blockIdx.z * KCHUNK;

    __shared__ float As[KCHUNK][68];   // [k][row], padded
    __shared__ float Bs[KCHUNK][68];

    const int t  = threadIdx.x;
    const int lr = t >> 2;            // 0..63 : row within tile
    const int c4 = (t & 3) * 4;       // 0,4,8,12 : k sub-offset

#pragma unroll
    for (int i = 0; i < 4; i++) {
        const int k0 = c4 + 16 * i;
        float4 va = *(const float4*)(X + (size_t)(tileR + lr) * DF + kBase + k0);
        As[k0 + 0][lr] = va.x; As[k0 + 1][lr] = va.y;
        As[k0 + 2][lr] = va.z; As[k0 + 3][lr] = va.w;
        float4 vb = *(const float4*)(X + (size_t)(tileC + lr) * DF + kBase + k0);
        Bs[k0 + 0][lr] = vb.x; Bs[k0 + 1][lr] = vb.y;
        Bs[k0 + 2][lr] = vb.z; Bs[k0 + 3][lr] = vb.w;
    }
    __syncthreads();

    const int ty = t >> 4;            // 0..15
    const int tx = t & 15;            // 0..15
    const int r0 = ty * 4;
    const int c0 = tx * 4;

    float acc[4][4] = {};
#pragma unroll 16
    for (int k = 0; k < KCHUNK; k++) {
        float4 a = *(const float4*)&As[k][r0];
        float4 b = *(const float4*)&Bs[k][c0];
        const float av[4] = {a.x, a.y, a.z, a.w};
        const float bv[4] = {b.x, b.y, b.z, b.w};
#pragma unroll
        for (int ii = 0; ii < 4; ii++)
#pragma unroll
            for (int jj = 0; jj < 4; jj++)
                acc[ii][jj] = fmaf(av[ii], bv[jj], acc[ii][jj]);
    }

    float* dst = g_Gp + (size_t)blockIdx.z * (B * B);
#pragma unroll
    for (int ii = 0; ii < 4; ii++)
#pragma unroll
        for (int jj = 0; jj < 4; jj++)
            dst[(tileR + r0 + ii) * B + tileC + c0 + jj] = acc[ii][jj];
}

// ---------------------------------------------------------------------------
// Kernel R: deterministic split-K reduction. grid 32, block 512.
// ---------------------------------------------------------------------------
__global__ __launch_bounds__(512) void gram_reduce() {
    const int idx = blockIdx.x * 512 + threadIdx.x;   // 0..16383
    float s = 0.f;
#pragma unroll
    for (int z = 0; z < KSPLIT; z++) s += g_Gp[z * (B * B) + idx];
    g_G[idx] = s;
}

// ---------------------------------------------------------------------------
// Kernel B: per-group loss. grid 16 (one per (target,sub) anchor class),
// block 128 (thread k = column index). All angles derived from G:
//   ang[j,k] = (G[j,k] - S[j] - S[k] + q) * inv_n[j] * inv_n[k]
// Pairs: (j0, j1) = (16p+r, 16p+8+r), p != target, r in [0,8).
// ---------------------------------------------------------------------------
__global__ __launch_bounds__(128) void loss_partial() {
    const int g    = blockIdx.x;
    const int tgt  = g >> 1;
    const int sb   = g & 1;
    const int base = tgt * 16 + sb * 8;   // rows of this group's center
    const int k    = threadIdx.x;

    __shared__ float sS[B];
    __shared__ float sInv[B];
    __shared__ float red[4];

    float sk = 0.f;
#pragma unroll
    for (int i = 0; i < 8; i++) sk += g_G[(base + i) * B + k];
    sk *= 0.125f;
    sS[k] = sk;
    __syncthreads();

    float q = 0.f;
#pragma unroll
    for (int i = 0; i < 8; i++) q += sS[base + i];
    q *= 0.125f;

    const float n2 = g_G[k * B + k] - 2.f * sk + q;
    const float nr = sqrtf(fmaxf(n2, 0.f));
    sInv[k] = 1.f / fmaxf(nr, 1e-12f);
    __syncthreads();

    const float invk = sInv[k];
    float acc = 0.f;
    for (int p = 0; p < 8; p++) {
        if (p == tgt) continue;
        const int jb = p * 16;
#pragma unroll
        for (int r = 0; r < 8; r++) {
            const int j0 = jb + r;
            const int j1 = j0 + 8;
            const float a0 = (g_G[j0 * B + k] - sS[j0] - sk + q) * (sInv[j0] * invk);
            const float a1 = (g_G[j1 * B + k] - sS[j1] - sk + q) * (sInv[j1] * invk);
            acc += fabsf(a0 - a1);
        }
    }

    // Block reduction (deterministic).
#pragma unroll
    for (int o = 16; o > 0; o >>= 1) acc += __shfl_down_sync(0xffffffffu, acc, o);
    if ((k & 31) == 0) red[k >> 5] = acc;
    __syncthreads();
    if (k == 0) g_partials[g] = (red[0] + red[1]) + (red[2] + red[3]);
}

// ---------------------------------------------------------------------------
// Kernel C: final scalar. loss = sum(partials) / (16*56*128).
// ---------------------------------------------------------------------------
__global__ void loss_final(float* __restrict__ out) {
    float v = (threadIdx.x < 16) ? g_partials[threadIdx.x] : 0.f;
#pragma unroll
    for (int o = 16; o > 0; o >>= 1) v += __shfl_down_sync(0xffffffffu, v, o);
    if (threadIdx.x == 0) out[0] = v * (1.0f / 114688.0f);
}

extern "C" void kernel_launch(void* const* d_in, const int* in_sizes, int n_in,
                              void* d_out, int out_size) {
    const float* X = (const float*)d_in[0];   // [128, 2048] fp32
    float* out = (float*)d_out;               // scalar loss

    gram_partial<<<dim3(2, 2, KSPLIT), 256>>>(X);
    gram_reduce<<<32, 512>>>();
    loss_partial<<<16, 128>>>();
    loss_final<<<1, 32>>>(out);
}

// round 2
// speedup vs baseline: 1.2737x; 1.2737x over previous
#include <cuda_runtime.h>

#define B 128
#define DF 2048
#define KSPLIT 32
#define KCHUNK 64           // DF / KSPLIT
#define NBLOCKS 128
#define NTHREADS 256

// Scratch (static device globals, zero-initialized; no allocation).
__device__ float g_Gp[KSPLIT * B * B];   // split-K partial Gram
__device__ float g_G[B * B];             // reduced Gram
__device__ float g_partials[16];         // per-group loss sums
__device__ unsigned g_bar[2];            // monotonic barrier counters (never reset)
__device__ unsigned g_fin;               // monotonic finalize counter (never reset)

// Monotonic grid barrier: no reset required across graph replays.
// 2^32 % n == 0 for n in {128}, so position math survives wraparound.
__device__ __forceinline__ void grid_barrier(int which) {
    __syncthreads();
    if (threadIdx.x == 0) {
        __threadfence();
        unsigned old = atomicAdd(&g_bar[which], 1u);
        unsigned target = old - (old & (NBLOCKS - 1u)) + NBLOCKS;
        while ((int)(*(volatile unsigned*)&g_bar[which] - target) < 0) {
            __nanosleep(64);
        }
    }
    __syncthreads();
}

__global__ __launch_bounds__(NTHREADS) void fused_angle_loss(
    const float* __restrict__ X, float* __restrict__ out) {

    __shared__ float smemBuf[2 * KCHUNK * 68];   // 34.8KB, reused across phases
    const int b = blockIdx.x;
    const int t = threadIdx.x;

    // ============================ Phase 1: split-K Gram =====================
    // block b: z = b>>2 (K chunk), tile = b&3 -> 64x64 output tile.
    {
        const int z     = b >> 2;
        const int tileR = ((b >> 1) & 1) * 64;
        const int tileC = (b & 1) * 64;
        const int kBase = z * KCHUNK;

        float (*As)[68] = (float(*)[68])smemBuf;
        float (*Bs)[68] = (float(*)[68])(smemBuf + KCHUNK * 68);

        const int lr = t >> 2;            // 0..63 row within tile
        const int c4 = (t & 3) * 4;       // k sub-offset
#pragma unroll
        for (int i = 0; i < 4; i++) {
            const int k0 = c4 + 16 * i;
            float4 va = *(const float4*)(X + (size_t)(tileR + lr) * DF + kBase + k0);
            As[k0 + 0][lr] = va.x; As[k0 + 1][lr] = va.y;
            As[k0 + 2][lr] = va.z; As[k0 + 3][lr] = va.w;
            float4 vb = *(const float4*)(X + (size_t)(tileC + lr) * DF + kBase + k0);
            Bs[k0 + 0][lr] = vb.x; Bs[k0 + 1][lr] = vb.y;
            Bs[k0 + 2][lr] = vb.z; Bs[k0 + 3][lr] = vb.w;
        }
        __syncthreads();

        const int r0 = (t >> 4) * 4;
        const int c0 = (t & 15) * 4;
        float acc[4][4] = {};
#pragma unroll 16
        for (int k = 0; k < KCHUNK; k++) {
            float4 a = *(const float4*)&As[k][r0];
            float4 bb = *(const float4*)&Bs[k][c0];
            const float av[4] = {a.x, a.y, a.z, a.w};
            const float bv[4] = {bb.x, bb.y, bb.z, bb.w};
#pragma unroll
            for (int ii = 0; ii < 4; ii++)
#pragma unroll
                for (int jj = 0; jj < 4; jj++)
                    acc[ii][jj] = fmaf(av[ii], bv[jj], acc[ii][jj]);
        }

        float* dst = g_Gp + (size_t)z * (B * B);
#pragma unroll
        for (int ii = 0; ii < 4; ii++) {
            float4 v = make_float4(acc[ii][0], acc[ii][1], acc[ii][2], acc[ii][3]);
            *(float4*)&dst[(tileR + r0 + ii) * B + tileC + c0] = v;
        }
    }

    grid_barrier(0);

    // ===================== Phase 2: deterministic split-K reduce ============
    // blocks 0..31, threads 0..127: each thread one float4 column across 32 z.
    if (b < 32 && t < 128) {
        const int f4 = b * 128 + t;              // 0..4095 float4 index
        const float4* src = (const float4*)g_Gp;
        float4 s = make_float4(0.f, 0.f, 0.f, 0.f);
#pragma unroll
        for (int z = 0; z < KSPLIT; z++) {
            float4 v = __ldcg(src + (size_t)z * 4096 + f4);
            s.x += v.x; s.y += v.y; s.z += v.z; s.w += v.w;
        }
        ((float4*)g_G)[f4] = s;
    }

    grid_barrier(1);

    if (b >= 16) return;

    // ======================= Phase 3: per-group loss ========================
    // block = group g (target, sub). 256 threads: k = t&127, half h = t>>7
    // handles r in [4h, 4h+4) of each pair octet.
    {
        const int g    = b;
        const int tgt  = g >> 1;
        const int sb   = g & 1;
        const int base = tgt * 16 + sb * 8;
        const int k    = t & 127;
        const int h    = t >> 7;

        float* sS   = smemBuf;          // [128]
        float* sInv = smemBuf + 128;    // [128]
        float* red  = smemBuf + 256;    // [8]

        if (h == 0) {
            float sk = 0.f;
#pragma unroll
            for (int i = 0; i < 8; i++) sk += __ldcg(&g_G[(base + i) * B + k]);
            sS[k] = sk * 0.125f;
        }
        __syncthreads();

        float q = 0.f;
#pragma unroll
        for (int i = 0; i < 8; i++) q += sS[base + i];
        q *= 0.125f;

        if (h == 0) {
            const float n2 = __ldcg(&g_G[k * B + k]) - 2.f * sS[k] + q;
            const float nr = sqrtf(fmaxf(n2, 0.f));
            sInv[k] = 1.f / fmaxf(nr, 1e-12f);
        }
        __syncthreads();

        const float sk   = sS[k];
        const float invk = sInv[k];
        float acc = 0.f;
#pragma unroll
        for (int p = 0; p < 8; p++) {
            if (p == tgt) continue;
            const int jb = p * 16 + h * 4;
#pragma unroll
            for (int r = 0; r < 4; r++) {
                const int j0 = jb + r;
                const int j1 = j0 + 8;
                const float a0 = (__ldcg(&g_G[j0 * B + k]) - sS[j0] - sk + q) * (sInv[j0] * invk);
                const float a1 = (__ldcg(&g_G[j1 * B + k]) - sS[j1] - sk + q) * (sInv[j1] * invk);
                acc += fabsf(a0 - a1);
            }
        }

        // Deterministic block reduction over 256 threads.
#pragma unroll
        for (int o = 16; o > 0; o >>= 1) acc += __shfl_down_sync(0xffffffffu, acc, o);
        if ((t & 31) == 0) red[t >> 5] = acc;
        __syncthreads();

        if (t == 0) {
            float s = 0.f;
#pragma unroll
            for (int w = 0; w < 8; w++) s += red[w];
            g_partials[g] = s;
            __threadfence();
            unsigned old = atomicAdd(&g_fin, 1u);
            if ((old & 15u) == 15u) {
                // Last group block finalizes: fixed-order sum -> deterministic.
                float tot = 0.f;
#pragma unroll
                for (int i = 0; i < 16; i++) tot += __ldcg(&g_partials[i]);
                out[0] = tot * (1.0f / 114688.0f);
            }
        }
    }
}

extern "C" void kernel_launch(void* const* d_in, const int* in_sizes, int n_in,
                              void* d_out, int out_size) {
    const float* X = (const float*)d_in[0];   // [128, 2048] fp32
    float* out = (float*)d_out;               // scalar loss

    fused_angle_loss<<<NBLOCKS, NTHREADS>>>(X, out);
}